// round 1
// baseline (speedup 1.0000x reference)
#include <cuda_runtime.h>
#include <math.h>
#include <stdint.h>

#define D 128
#define N_MAX 50048
#define MLP_TILE 128

// Scratch (device globals — no allocation allowed)
__device__ float g_deg[N_MAX];
__device__ float g_norm[N_MAX];
__device__ float g_agg[(size_t)N_MAX * D];

// ---------------------------------------------------------------------------
// 1) in-degree count over dst
// ---------------------------------------------------------------------------
__global__ void deg_kernel(const int* __restrict__ dst, int E) {
    int i = blockIdx.x * blockDim.x + threadIdx.x;
    if (i < E) atomicAdd(&g_deg[dst[i]], 1.0f);
}

// ---------------------------------------------------------------------------
// 2) norm = rsqrt(max(deg,1))
// ---------------------------------------------------------------------------
__global__ void norm_kernel(int N) {
    int i = blockIdx.x * blockDim.x + threadIdx.x;
    if (i < N) g_norm[i] = rsqrtf(fmaxf(g_deg[i], 1.0f));
}

// ---------------------------------------------------------------------------
// 3) SPMM: agg[dst] += x[src] * norm[src]
//    One warp per edge; each lane handles a float4 chunk (32 * 4 = 128 feats).
//    Scatter via vectorized no-return reduction (red.global.add.v4.f32).
// ---------------------------------------------------------------------------
__global__ void spmm_kernel(const float* __restrict__ x,
                            const int* __restrict__ src,
                            const int* __restrict__ dst,
                            int E) {
    int t = blockIdx.x * blockDim.x + threadIdx.x;
    int e = t >> 5;
    int lane = t & 31;
    if (e >= E) return;
    int s = __ldg(&src[e]);
    int d = __ldg(&dst[e]);
    float ns = __ldg((const float*)&g_norm[s]);
    float4 v = __ldg(((const float4*)(x + (size_t)s * D)) + lane);
    v.x *= ns; v.y *= ns; v.z *= ns; v.w *= ns;
    float* p = &g_agg[(size_t)d * D + lane * 4];
    asm volatile("red.global.add.v4.f32 [%0], {%1, %2, %3, %4};"
                 :: "l"(p), "f"(v.x), "f"(v.y), "f"(v.z), "f"(v.w)
                 : "memory");
}

// ---------------------------------------------------------------------------
// 4) Fused epilogue: h = agg * norm[dst];
//    h1 = relu(h @ w_conv^T + b_conv); out = relu(h1 @ w_lin^T + b_lin)
//    Block: 256 threads (16x16), 128-node tile, 8x8 register tiling.
//    Smem: inT[k][n] 64KB + w1T[k][o] 64KB + w2T[k][o] 64KB = 192KB.
// ---------------------------------------------------------------------------
__global__ void __launch_bounds__(256, 1)
mlp_kernel(const float* __restrict__ wc, const float* __restrict__ bc,
           const float* __restrict__ wl, const float* __restrict__ bl,
           float* __restrict__ out, int N) {
    extern __shared__ float sm[];
    float* s_in = sm;                 // [128][128]  (transposed: [k][n])
    float* s_w1 = sm + 128 * 128;     // [128][128]  (transposed: [k][o])
    float* s_w2 = sm + 2 * 128 * 128; // [128][128]  (transposed: [k][o])

    const int tid = threadIdx.x;
    const int n0 = blockIdx.x * MLP_TILE;

    // Load both weights transposed (gmem [o][k] row-major -> smem [k][o])
    for (int i = tid; i < 128 * 128; i += 256) {
        int o = i >> 7, k = i & 127;
        s_w1[k * 128 + o] = wc[i];
        s_w2[k * 128 + o] = wl[i];
    }
    // Load input tile scaled by norm[dst], transposed to [k][n]
    for (int i = tid; i < MLP_TILE * 128; i += 256) {
        int n = i >> 7, k = i & 127;
        int gn = n0 + n;
        float v = 0.0f;
        if (gn < N) v = g_agg[(size_t)gn * 128 + k] * g_norm[gn];
        s_in[k * 128 + n] = v;
    }
    __syncthreads();

    const int tx = tid & 15;   // output tile  (o = tx*8 .. +8)
    const int ty = tid >> 4;   // node tile    (n = ty*8 .. +8)

    float acc[8][8];

    // ---------------- GEMM 1 ----------------
    #pragma unroll
    for (int i = 0; i < 8; i++)
        #pragma unroll
        for (int j = 0; j < 8; j++) acc[i][j] = 0.0f;

    #pragma unroll 4
    for (int k = 0; k < 128; k++) {
        float4 a0 = *(const float4*)&s_in[k * 128 + ty * 8];
        float4 a1 = *(const float4*)&s_in[k * 128 + ty * 8 + 4];
        float4 b0 = *(const float4*)&s_w1[k * 128 + tx * 8];
        float4 b1 = *(const float4*)&s_w1[k * 128 + tx * 8 + 4];
        float a[8] = {a0.x, a0.y, a0.z, a0.w, a1.x, a1.y, a1.z, a1.w};
        float b[8] = {b0.x, b0.y, b0.z, b0.w, b1.x, b1.y, b1.z, b1.w};
        #pragma unroll
        for (int i = 0; i < 8; i++)
            #pragma unroll
            for (int j = 0; j < 8; j++) acc[i][j] = fmaf(a[i], b[j], acc[i][j]);
    }

    __syncthreads();  // everyone done reading s_in

    // relu(acc + bias), write back transposed into s_in as [o][n] for GEMM2
    #pragma unroll
    for (int j = 0; j < 8; j++) {
        float bias = bc[tx * 8 + j];
        #pragma unroll
        for (int i = 0; i < 8; i++) {
            float v = fmaxf(acc[i][j] + bias, 0.0f);
            s_in[(tx * 8 + j) * 128 + (ty * 8 + i)] = v;
        }
    }
    __syncthreads();

    // ---------------- GEMM 2 ----------------
    #pragma unroll
    for (int i = 0; i < 8; i++)
        #pragma unroll
        for (int j = 0; j < 8; j++) acc[i][j] = 0.0f;

    #pragma unroll 4
    for (int k = 0; k < 128; k++) {
        float4 a0 = *(const float4*)&s_in[k * 128 + ty * 8];
        float4 a1 = *(const float4*)&s_in[k * 128 + ty * 8 + 4];
        float4 b0 = *(const float4*)&s_w2[k * 128 + tx * 8];
        float4 b1 = *(const float4*)&s_w2[k * 128 + tx * 8 + 4];
        float a[8] = {a0.x, a0.y, a0.z, a0.w, a1.x, a1.y, a1.z, a1.w};
        float b[8] = {b0.x, b0.y, b0.z, b0.w, b1.x, b1.y, b1.z, b1.w};
        #pragma unroll
        for (int i = 0; i < 8; i++)
            #pragma unroll
            for (int j = 0; j < 8; j++) acc[i][j] = fmaf(a[i], b[j], acc[i][j]);
    }

    // relu(acc + bias) -> gmem
    #pragma unroll
    for (int j = 0; j < 8; j++) {
        float bias = bl[tx * 8 + j];
        #pragma unroll
        for (int i = 0; i < 8; i++) {
            int gn = n0 + ty * 8 + i;
            if (gn < N)
                out[(size_t)gn * 128 + tx * 8 + j] = fmaxf(acc[i][j] + bias, 0.0f);
        }
    }
}

// ---------------------------------------------------------------------------
extern "C" void kernel_launch(void* const* d_in, const int* in_sizes, int n_in,
                              void* d_out, int out_size) {
    const float* x    = (const float*)d_in[0];
    const int*   src  = (const int*)  d_in[1];
    const int*   dst  = (const int*)  d_in[2];
    const float* wc   = (const float*)d_in[3];
    const float* bc   = (const float*)d_in[4];
    const float* wl   = (const float*)d_in[5];
    const float* bl   = (const float*)d_in[6];
    float* out = (float*)d_out;

    const int N = in_sizes[0] / D;
    const int E = in_sizes[1];

    void* p_deg = nullptr;
    void* p_agg = nullptr;
    cudaGetSymbolAddress(&p_deg, g_deg);
    cudaGetSymbolAddress(&p_agg, g_agg);
    cudaMemsetAsync(p_deg, 0, (size_t)N * sizeof(float));
    cudaMemsetAsync(p_agg, 0, (size_t)N * D * sizeof(float));

    deg_kernel<<<(E + 255) / 256, 256>>>(dst, E);
    norm_kernel<<<(N + 255) / 256, 256>>>(N);

    // one warp per edge
    long long spmm_threads = (long long)E * 32;
    int spmm_blocks = (int)((spmm_threads + 255) / 256);
    spmm_kernel<<<spmm_blocks, 256>>>(x, src, dst, E);

    const int smem_bytes = 3 * 128 * 128 * sizeof(float);  // 192KB
    cudaFuncSetAttribute(mlp_kernel, cudaFuncAttributeMaxDynamicSharedMemorySize, smem_bytes);
    mlp_kernel<<<(N + MLP_TILE - 1) / MLP_TILE, 256, smem_bytes>>>(wc, bc, wl, bl, out, N);
}

// round 2
// speedup vs baseline: 1.3874x; 1.3874x over previous
#include <cuda_runtime.h>
#include <math.h>
#include <stdint.h>

#define D 128
#define N_MAX 50048
#define TILE_N 192
#define MLP_THREADS 384
#define SIN 196   // s_in row stride (floats), mult of 4 for vec4 alignment
#define SW  132   // s_w row stride

// Scratch (device globals — no allocation allowed)
__device__ float g_deg[N_MAX];
__device__ float g_norm[N_MAX];
__device__ float g_agg[(size_t)N_MAX * D];

// ---------------------------------------------------------------------------
// packed f32x2 helpers (Blackwell sm_103a)
// ---------------------------------------------------------------------------
__device__ __forceinline__ unsigned long long pk2(float lo, float hi) {
    unsigned long long r;
    asm("mov.b64 %0, {%1, %2};" : "=l"(r) : "f"(lo), "f"(hi));
    return r;
}
__device__ __forceinline__ unsigned long long fma2(unsigned long long a,
                                                   unsigned long long b,
                                                   unsigned long long c) {
    unsigned long long d;
    asm("fma.rn.f32x2 %0, %1, %2, %3;" : "=l"(d) : "l"(a), "l"(b), "l"(c));
    return d;
}
__device__ __forceinline__ float2 upk2(unsigned long long v) {
    float2 f;
    asm("mov.b64 {%0, %1}, %2;" : "=f"(f.x), "=f"(f.y) : "l"(v));
    return f;
}

// ---------------------------------------------------------------------------
// 1) in-degree count over dst
// ---------------------------------------------------------------------------
__global__ void deg_kernel(const int* __restrict__ dst, int E) {
    int i = blockIdx.x * blockDim.x + threadIdx.x;
    if (i < E) atomicAdd(&g_deg[dst[i]], 1.0f);
}

// ---------------------------------------------------------------------------
// 2) norm = rsqrt(max(deg,1))
// ---------------------------------------------------------------------------
__global__ void norm_kernel(int N) {
    int i = blockIdx.x * blockDim.x + threadIdx.x;
    if (i < N) g_norm[i] = rsqrtf(fmaxf(g_deg[i], 1.0f));
}

// ---------------------------------------------------------------------------
// 3) SPMM: agg[dst] += x[src] * norm[src]  (one warp per edge, red.v4 scatter)
// ---------------------------------------------------------------------------
__global__ void spmm_kernel(const float* __restrict__ x,
                            const int* __restrict__ src,
                            const int* __restrict__ dst,
                            int E) {
    int t = blockIdx.x * blockDim.x + threadIdx.x;
    int e = t >> 5;
    int lane = t & 31;
    if (e >= E) return;
    int s = __ldg(&src[e]);
    int d = __ldg(&dst[e]);
    float ns = __ldg((const float*)&g_norm[s]);
    float4 v = __ldg(((const float4*)(x + (size_t)s * D)) + lane);
    v.x *= ns; v.y *= ns; v.z *= ns; v.w *= ns;
    float* p = &g_agg[(size_t)d * D + lane * 4];
    asm volatile("red.global.add.v4.f32 [%0], {%1, %2, %3, %4};"
                 :: "l"(p), "f"(v.x), "f"(v.y), "f"(v.z), "f"(v.w)
                 : "memory");
}

// ---------------------------------------------------------------------------
// 4) Fused 2-layer MLP with packed f32x2 FMAs.
//    Tile: 192 nodes x 128 out. 384 threads (tx=o-group 0..15, ty=n-group 0..23),
//    each thread computes 8 nodes x 8 outs (as 8x4 f32x2 pairs).
// ---------------------------------------------------------------------------
__global__ void __launch_bounds__(MLP_THREADS, 1)
mlp_kernel(const float* __restrict__ wc, const float* __restrict__ bc,
           const float* __restrict__ wl, const float* __restrict__ bl,
           float* __restrict__ out, int N) {
    extern __shared__ float sm[];
    float* s_in = sm;                  // [128][SIN]  ([k][n]) ; later s_h [n][128]
    float* s_w  = sm + 128 * SIN;      // [128][SW]   ([k][o])

    const int tid = threadIdx.x;
    const int n0 = blockIdx.x * TILE_N;
    const int tx = tid & 15;    // o-group
    const int ty = tid >> 4;    // n-group (0..23)

    // ---- load w1 transposed ([o][k] -> [k][o]) ----
    for (int i = tid; i < 128 * 128; i += MLP_THREADS) {
        int o = i >> 7, k = i & 127;
        s_w[k * SW + o] = wc[i];
    }
    // ---- load input tile, scaled by norm[dst], transposed to [k][n] ----
    for (int i = tid; i < TILE_N * 128; i += MLP_THREADS) {
        int n = i >> 7, k = i & 127;
        int gn = n0 + n;
        float v = 0.0f;
        if (gn < N) v = g_agg[(size_t)gn * 128 + k] * g_norm[gn];
        s_in[k * SIN + n] = v;
    }
    __syncthreads();

    unsigned long long acc[8][4];

    // ================= GEMM 1 =================
    #pragma unroll
    for (int i = 0; i < 8; i++)
        #pragma unroll
        for (int j = 0; j < 4; j++) acc[i][j] = 0ull;

    #pragma unroll 2
    for (int k = 0; k < 128; k++) {
        float4 a0 = *(const float4*)&s_in[k * SIN + ty * 8];
        float4 a1 = *(const float4*)&s_in[k * SIN + ty * 8 + 4];
        float4 b0 = *(const float4*)&s_w[k * SW + tx * 8];
        float4 b1 = *(const float4*)&s_w[k * SW + tx * 8 + 4];
        unsigned long long bp[4] = {pk2(b0.x, b0.y), pk2(b0.z, b0.w),
                                    pk2(b1.x, b1.y), pk2(b1.z, b1.w)};
        float a[8] = {a0.x, a0.y, a0.z, a0.w, a1.x, a1.y, a1.z, a1.w};
        #pragma unroll
        for (int i = 0; i < 8; i++) {
            unsigned long long ap = pk2(a[i], a[i]);
            #pragma unroll
            for (int j = 0; j < 4; j++) acc[i][j] = fma2(ap, bp[j], acc[i][j]);
        }
    }

    __syncthreads();  // all GEMM1 reads of s_in / s_w complete

    // ---- h1 = relu(acc + bc), stage as s_h[n][o]; also load w2 ----
    float* s_h = s_in;  // [TILE_N][128]
    {
        float4 bb0 = *(const float4*)&bc[tx * 8];
        float4 bb1 = *(const float4*)&bc[tx * 8 + 4];
        float bias[8] = {bb0.x, bb0.y, bb0.z, bb0.w, bb1.x, bb1.y, bb1.z, bb1.w};
        #pragma unroll
        for (int i = 0; i < 8; i++) {
            float h[8];
            #pragma unroll
            for (int j = 0; j < 4; j++) {
                float2 v = upk2(acc[i][j]);
                h[2 * j]     = fmaxf(v.x + bias[2 * j], 0.0f);
                h[2 * j + 1] = fmaxf(v.y + bias[2 * j + 1], 0.0f);
            }
            float* p = &s_h[(ty * 8 + i) * 128 + tx * 8];
            *(float4*)p       = make_float4(h[0], h[1], h[2], h[3]);
            *(float4*)(p + 4) = make_float4(h[4], h[5], h[6], h[7]);
        }
    }
    for (int i = tid; i < 128 * 128; i += MLP_THREADS) {
        int o = i >> 7, k = i & 127;
        s_w[k * SW + o] = wl[i];
    }
    __syncthreads();

    // ================= GEMM 2 =================
    #pragma unroll
    for (int i = 0; i < 8; i++)
        #pragma unroll
        for (int j = 0; j < 4; j++) acc[i][j] = 0ull;

    for (int k = 0; k < 128; k += 4) {
        float4 av[8];
        #pragma unroll
        for (int i = 0; i < 8; i++)
            av[i] = *(const float4*)&s_h[(ty * 8 + i) * 128 + k];
        #pragma unroll
        for (int kk = 0; kk < 4; kk++) {
            float4 b0 = *(const float4*)&s_w[(k + kk) * SW + tx * 8];
            float4 b1 = *(const float4*)&s_w[(k + kk) * SW + tx * 8 + 4];
            unsigned long long bp[4] = {pk2(b0.x, b0.y), pk2(b0.z, b0.w),
                                        pk2(b1.x, b1.y), pk2(b1.z, b1.w)};
            #pragma unroll
            for (int i = 0; i < 8; i++) {
                float a = (kk == 0) ? av[i].x : (kk == 1) ? av[i].y
                         : (kk == 2) ? av[i].z : av[i].w;
                unsigned long long ap = pk2(a, a);
                #pragma unroll
                for (int j = 0; j < 4; j++) acc[i][j] = fma2(ap, bp[j], acc[i][j]);
            }
        }
    }

    // ---- relu(acc + bl) -> gmem ----
    {
        float4 bb0 = *(const float4*)&bl[tx * 8];
        float4 bb1 = *(const float4*)&bl[tx * 8 + 4];
        float bias[8] = {bb0.x, bb0.y, bb0.z, bb0.w, bb1.x, bb1.y, bb1.z, bb1.w};
        #pragma unroll
        for (int i = 0; i < 8; i++) {
            int gn = n0 + ty * 8 + i;
            if (gn < N) {
                float h[8];
                #pragma unroll
                for (int j = 0; j < 4; j++) {
                    float2 v = upk2(acc[i][j]);
                    h[2 * j]     = fmaxf(v.x + bias[2 * j], 0.0f);
                    h[2 * j + 1] = fmaxf(v.y + bias[2 * j + 1], 0.0f);
                }
                float* p = &out[(size_t)gn * 128 + tx * 8];
                *(float4*)p       = make_float4(h[0], h[1], h[2], h[3]);
                *(float4*)(p + 4) = make_float4(h[4], h[5], h[6], h[7]);
            }
        }
    }
}

// ---------------------------------------------------------------------------
extern "C" void kernel_launch(void* const* d_in, const int* in_sizes, int n_in,
                              void* d_out, int out_size) {
    const float* x    = (const float*)d_in[0];
    const int*   src  = (const int*)  d_in[1];
    const int*   dst  = (const int*)  d_in[2];
    const float* wc   = (const float*)d_in[3];
    const float* bc   = (const float*)d_in[4];
    const float* wl   = (const float*)d_in[5];
    const float* bl   = (const float*)d_in[6];
    float* out = (float*)d_out;

    const int N = in_sizes[0] / D;
    const int E = in_sizes[1];

    void* p_deg = nullptr;
    void* p_agg = nullptr;
    cudaGetSymbolAddress(&p_deg, g_deg);
    cudaGetSymbolAddress(&p_agg, g_agg);
    cudaMemsetAsync(p_deg, 0, (size_t)N * sizeof(float));
    cudaMemsetAsync(p_agg, 0, (size_t)N * D * sizeof(float));

    deg_kernel<<<(E + 255) / 256, 256>>>(dst, E);
    norm_kernel<<<(N + 255) / 256, 256>>>(N);

    long long spmm_threads = (long long)E * 32;
    int spmm_blocks = (int)((spmm_threads + 255) / 256);
    spmm_kernel<<<spmm_blocks, 256>>>(x, src, dst, E);

    const int smem_bytes = (128 * SIN + 128 * SW) * sizeof(float);  // ~164KB
    cudaFuncSetAttribute(mlp_kernel, cudaFuncAttributeMaxDynamicSharedMemorySize, smem_bytes);
    int mlp_blocks = (N + TILE_N - 1) / TILE_N;
    mlp_kernel<<<mlp_blocks, MLP_THREADS, smem_bytes>>>(wc, bc, wl, bl, out, N);
}